// round 8
// baseline (speedup 1.0000x reference)
#include <cuda_runtime.h>

typedef unsigned long long u64;

// Problem constants: N=2, C=2, H=W=D=64, R=3, WEIGHT=1, SIGMA_XY=6, SIGMA_IMG=0.1
static constexpr int H = 64, W = 64, D = 64, NN = 2;
static constexpr int NBLK = 2 * 64 * 8;   // n(2) * i(64) * jc(8) = 1024 blocks

// smem tile: 4 rows (i..i+3) x 14 cols (j-3..j+10) x 16 float4 (64 d-values)
static constexpr int TC = 14;             // tile cols
static constexpr int TILE = 4 * TC * 16;  // 896 float4 per array

__device__ float g_partials[NBLK];
__device__ unsigned int g_count = 0;

__device__ __forceinline__ float ex2f(float x) {
    float y;
    asm("ex2.approx.ftz.f32 %0, %1;" : "=f"(y) : "f"(x));
    return y;
}
__device__ __forceinline__ u64 pk(float a, float b) {
    u64 r; asm("mov.b64 %0, {%1, %2};" : "=l"(r) : "f"(a), "f"(b)); return r;
}
__device__ __forceinline__ void upk(float& a, float& b, u64 v) {
    asm("mov.b64 {%0, %1}, %2;" : "=f"(a), "=f"(b) : "l"(v));
}
__device__ __forceinline__ u64 fma2(u64 a, u64 b, u64 c) {
    u64 r; asm("fma.rn.f32x2 %0, %1, %2, %3;" : "=l"(r) : "l"(a), "l"(b), "l"(c)); return r;
}
__device__ __forceinline__ u64 add2(u64 a, u64 b) {
    u64 r; asm("add.rn.f32x2 %0, %1, %2;" : "=l"(r) : "l"(a), "l"(b)); return r;
}
__device__ __forceinline__ u64 mul2(u64 a, u64 b) {
    u64 r; asm("mul.rn.f32x2 %0, %1, %2;" : "=l"(r) : "l"(a), "l"(b)); return r;
}

// KS = sqrt(50 * log2(e))
#define KS 8.4932180864f
#define HALFL2E 0.0200373478f  /* 0.5/36 * log2(e) */
#define NEGBIG -1.0e30f

__global__ __launch_bounds__(128) void crf_main(
    const float* __restrict__ yg, const float* __restrict__ sg,
    float* __restrict__ out)
{
    __shared__ float4 ss[TILE];
    __shared__ float4 sy[TILE];

    const int d4 = threadIdx.x;          // 0..15  (4 d-values)
    const int ty = threadIdx.y;          // 0..7   (j within 8-col chunk)
    const int b  = blockIdx.x;
    const int jc = b & 7;
    const int i  = (b >> 3) & 63;
    const int n  = b >> 9;
    const int j  = jc * 8 + ty;
    const int tid = ty * 16 + d4;        // 0..127

    const float4* __restrict__ s4 = (const float4*)sg;
    const float4* __restrict__ y4 = (const float4*)yg;

    // ---- Stage tile: rows i..i+3, cols jc*8-3 .. jc*8+10, all 64 d ----
    // OOB cells get clamped-address data; they are never read by the mainloop.
    #pragma unroll
    for (int k = 0; k < TILE / 128; ++k) {
        const int idx = tid + k * 128;
        const int dd = idx & 15;
        const int rc = idx >> 4;              // 0..55
        const int c  = rc % TC;
        const int r  = rc / TC;
        const int gi = min(i + r, H - 1);
        const int gj = min(max(jc * 8 + c - 3, 0), W - 1);
        ss[idx] = s4[(n * H + gi) * (W * 16) + gj * 16 + dd];
        sy[idx] = y4[(n * 2 * H + gi) * (W * 16) + gj * 16 + dd];
    }
    __syncthreads();

    // center smem index: row 0, col ty+3
    const int cidx = (ty + 3) * 16 + d4;

    const float4 sc = ss[cidx];
    const float4 yc = sy[cidx];

    const u64 KS2  = pk(KS, KS);
    const u64 NKS2 = pk(-KS, -KS);

    const u64 s01 = pk(sc.x, sc.y), s23 = pk(sc.z, sc.w);
    const u64 na01 = mul2(NKS2, s01), na23 = mul2(NKS2, s23);  // -KS*sc
    const u64 pa01 = mul2(KS2,  s01), pa23 = mul2(KS2,  s23);  // +KS*sc

    u64 S1a = 0ull, S1b = 0ull;   // sum of k
    u64 S2a = 0ull, S2b = 0ull;   // sum of k*yq

    // One unordered-pair offset (positive half-window), branchless OOB.
    auto body = [&](int di, int dj) {
        const float lw = -(float)(di * di + dj * dj) * HALFL2E;
        const bool v = ((i + di) < H) & ((unsigned)(j + dj) < (unsigned)W);
        const int idx = v ? cidx + (di * TC + dj) * 16 : cidx;
        const float lwv = v ? lw : NEGBIG;
        const u64 lw2 = pk(lwv, lwv);

        const float4 sq = ss[idx];
        const float4 yq = sy[idx];
        const u64 sq01 = pk(sq.x, sq.y), sq23 = pk(sq.z, sq.w);
        const u64 yq01 = pk(yq.x, yq.y), yq23 = pk(yq.z, yq.w);

        {   const u64 t  = fma2(KS2,  sq01, na01);
            const u64 nt = fma2(NKS2, sq01, pa01);
            const u64 w  = fma2(t, nt, lw2);
            float w0, w1; upk(w0, w1, w);
            const u64 k = pk(ex2f(w0), ex2f(w1));
            S1a = add2(S1a, k);
            S2a = fma2(k, yq01, S2a); }
        {   const u64 t  = fma2(KS2,  sq23, na23);
            const u64 nt = fma2(NKS2, sq23, pa23);
            const u64 w  = fma2(t, nt, lw2);
            float w0, w1; upk(w0, w1, w);
            const u64 k = pk(ex2f(w0), ex2f(w1));
            S1b = add2(S1b, k);
            S2b = fma2(k, yq23, S2b); }
    };

    body(0, 1); body(0, 2); body(0, 3);
    body(1, -3); body(1, -2); body(1, -1); body(1, 0);
    body(1, 1); body(1, 2); body(1, 3);
    body(2, -3); body(2, -2); body(2, -1); body(2, 0);
    body(2, 1); body(2, 2); body(2, 3);
    body(3, -3); body(3, -2); body(3, -1); body(3, 0);
    body(3, 1); body(3, 2); body(3, 3);

    // Epilogue: acc = sum_lane [ yp*S1 + (1-2*yp)*S2 ],  then *2 (directed)
    float acc;
    {
        float s1_0, s1_1, s1_2, s1_3, s2_0, s2_1, s2_2, s2_3;
        upk(s1_0, s1_1, S1a); upk(s1_2, s1_3, S1b);
        upk(s2_0, s2_1, S2a); upk(s2_2, s2_3, S2b);
        float a = yc.x * s1_0 + fmaf(-2.0f * yc.x, s2_0, s2_0);
        a += yc.y * s1_1 + fmaf(-2.0f * yc.y, s2_1, s2_1);
        a += yc.z * s1_2 + fmaf(-2.0f * yc.z, s2_2, s2_2);
        a += yc.w * s1_3 + fmaf(-2.0f * yc.w, s2_3, s2_3);
        acc = a * 2.0f;
    }

    // Out-of-bounds slots: zero-padded features ->
    // k_oob = exp(-0.5*(fr^2+fc^2+fs^2)) per pixel, times OOB slot count.
    {
        const int ir = min(i + 3, H - 1) - max(i - 3, 0) + 1;
        const int ic = min(j + 3, W - 1) - max(j - 3, 0) + 1;
        const float cnt = (float)(49 - ir * ic);
        if (cnt > 0.0f) {
            const float cij = -(float)(i * i + j * j) * HALFL2E;
            float a0, a1, a2, a3;
            upk(a0, a1, na01); upk(a2, a3, na23);
            float e = ex2f(fmaf(a0, -a0, cij))
                    + ex2f(fmaf(a1, -a1, cij))
                    + ex2f(fmaf(a2, -a2, cij))
                    + ex2f(fmaf(a3, -a3, cij));
            acc = fmaf(cnt, e, acc);
        }
    }

    // ---- Block tree reduction (deterministic) ----
    __shared__ float red[128];
    __shared__ bool is_last;
    red[tid] = acc;
    __syncthreads();
    #pragma unroll
    for (int offr = 64; offr > 0; offr >>= 1) {
        if (tid < offr) red[tid] += red[tid + offr];
        __syncthreads();
    }

    // ---- Last-block-done global reduction (fixed order => deterministic) ----
    if (tid == 0) {
        g_partials[b] = red[0];
        __threadfence();
        unsigned int v = atomicAdd(&g_count, 1u);
        is_last = (v == (unsigned)(NBLK - 1));
    }
    __syncthreads();

    if (is_last) {
        __threadfence();
        __shared__ double dred[128];
        double sum = 0.0;
        #pragma unroll
        for (int k = 0; k < NBLK / 128; ++k)
            sum += (double)g_partials[tid + k * 128];
        dred[tid] = sum;
        __syncthreads();
        #pragma unroll
        for (int offr = 64; offr > 0; offr >>= 1) {
            if (tid < offr) dred[tid] += dred[tid + offr];
            __syncthreads();
        }
        if (tid == 0) {
            out[0] = (float)(dred[0] / (double)(NN * D * H * W));
            g_count = 0;   // reset for next graph replay
        }
    }
}

extern "C" void kernel_launch(void* const* d_in, const int* in_sizes, int n_in,
                              void* d_out, int out_size)
{
    const float* y = (const float*)d_in[0];   // (2,2,64,64,64) softmax
    const float* s = (const float*)d_in[1];   // (2,1,64,64,64) sample
    if (n_in >= 2 && in_sizes[0] == 2 * 1 * H * W * D) {
        const float* tmp = y; y = s; s = tmp;
    }

    dim3 blk(16, 8);
    crf_main<<<NBLK, blk>>>(y, s, (float*)d_out);
}

// round 9
// speedup vs baseline: 1.3042x; 1.3042x over previous
#include <cuda_runtime.h>

typedef unsigned long long u64;

// Problem constants: N=2, C=2, H=W=D=64, R=3, WEIGHT=1, SIGMA_XY=6, SIGMA_IMG=0.1
static constexpr int H = 64, W = 64, D = 64, NN = 2;
static constexpr int NBLK = 2 * 64 * 8;   // n(2) * i(64) * jc(8) = 1024 blocks

__device__ float g_sum = 0.0f;
__device__ unsigned int g_count = 0;

__device__ __forceinline__ float ex2f(float x) {
    float y;
    asm("ex2.approx.ftz.f32 %0, %1;" : "=f"(y) : "f"(x));
    return y;
}
__device__ __forceinline__ u64 pk(float a, float b) {
    u64 r; asm("mov.b64 %0, {%1, %2};" : "=l"(r) : "f"(a), "f"(b)); return r;
}
__device__ __forceinline__ void upk(float& a, float& b, u64 v) {
    asm("mov.b64 {%0, %1}, %2;" : "=f"(a), "=f"(b) : "l"(v));
}
__device__ __forceinline__ u64 fma2(u64 a, u64 b, u64 c) {
    u64 r; asm("fma.rn.f32x2 %0, %1, %2, %3;" : "=l"(r) : "l"(a), "l"(b), "l"(c)); return r;
}
__device__ __forceinline__ u64 add2(u64 a, u64 b) {
    u64 r; asm("add.rn.f32x2 %0, %1, %2;" : "=l"(r) : "l"(a), "l"(b)); return r;
}
__device__ __forceinline__ u64 mul2(u64 a, u64 b) {
    u64 r; asm("mul.rn.f32x2 %0, %1, %2;" : "=l"(r) : "l"(a), "l"(b)); return r;
}

// KS = sqrt(50 * log2(e))
#define KS 8.4932180864f
#define HALFL2E 0.0200373478f  /* 0.5/36 * log2(e) */
#define NEGBIG -1.0e30f

__global__ __launch_bounds__(128, 6) void crf_main(
    const float* __restrict__ yg, const float* __restrict__ sg,
    float* __restrict__ out)
{
    const int d4 = threadIdx.x;          // 0..15  (4 d-values)
    const int ty = threadIdx.y;          // 0..7   (j within 8-col chunk)
    const int b  = blockIdx.x;
    const int jc = b & 7;
    const int i  = (b >> 3) & 63;
    const int n  = b >> 9;
    const int j  = jc * 8 + ty;
    const int tid = ty * 16 + d4;        // 0..127

    const float4* __restrict__ s4 = (const float4*)sg;
    const float4* __restrict__ y4 = (const float4*)yg;

    // sample layout: ((n*H + i)*W + j)*D + d   -> float4 index
    const int bs = (n * H + i) * (W * 16) + j * 16 + d4;
    // y channel 0: (((n*2)*H + i)*W + j)*D + d
    const int by = (n * 2 * H + i) * (W * 16) + j * 16 + d4;

    const float4 sc = s4[bs];
    const float4 yc = y4[by];

    const u64 KS2  = pk(KS, KS);
    const u64 NKS2 = pk(-KS, -KS);

    const u64 s01 = pk(sc.x, sc.y), s23 = pk(sc.z, sc.w);
    const u64 na01 = mul2(NKS2, s01), na23 = mul2(NKS2, s23);  // -KS*sc
    const u64 pa01 = mul2(KS2,  s01), pa23 = mul2(KS2,  s23);  // +KS*sc

    u64 S1a = 0ull, S1b = 0ull;   // sum of k
    u64 S2a = 0ull, S2b = 0ull;   // sum of k*yq

    // Positive half-window offsets (unordered pairs; doubled at the end).
    constexpr int DI[24] = {0,0,0, 1,1,1,1,1,1,1, 2,2,2,2,2,2,2, 3,3,3,3,3,3,3};
    constexpr int DJ[24] = {1,2,3, -3,-2,-1,0,1,2,3, -3,-2,-1,0,1,2,3, -3,-2,-1,0,1,2,3};

    // 6 batches of 4 offsets: loads front-batched (8 LDG.128 in flight),
    // then compute. Branchless OOB: offset clamped to center, lw -> -1e30.
    #pragma unroll
    for (int g = 0; g < 6; ++g) {
        float4 SQ[4], YQ[4];
        u64 LW[4];
        #pragma unroll
        for (int m = 0; m < 4; ++m) {
            const int di = DI[4 * g + m];
            const int dj = DJ[4 * g + m];
            const float lw = -(float)(di * di + dj * dj) * HALFL2E;
            const bool v = ((i + di) < H) & ((unsigned)(j + dj) < (unsigned)W);
            const int off = v ? (di * W + dj) * 16 : 0;
            const float lwv = v ? lw : NEGBIG;
            LW[m] = pk(lwv, lwv);
            SQ[m] = s4[bs + off];
            YQ[m] = y4[by + off];
        }
        #pragma unroll
        for (int m = 0; m < 4; ++m) {
            const u64 sq01 = pk(SQ[m].x, SQ[m].y), sq23 = pk(SQ[m].z, SQ[m].w);
            const u64 yq01 = pk(YQ[m].x, YQ[m].y), yq23 = pk(YQ[m].z, YQ[m].w);

            {   const u64 t  = fma2(KS2,  sq01, na01);
                const u64 nt = fma2(NKS2, sq01, pa01);
                const u64 w  = fma2(t, nt, LW[m]);
                float w0, w1; upk(w0, w1, w);
                const u64 k = pk(ex2f(w0), ex2f(w1));
                S1a = add2(S1a, k);
                S2a = fma2(k, yq01, S2a); }
            {   const u64 t  = fma2(KS2,  sq23, na23);
                const u64 nt = fma2(NKS2, sq23, pa23);
                const u64 w  = fma2(t, nt, LW[m]);
                float w0, w1; upk(w0, w1, w);
                const u64 k = pk(ex2f(w0), ex2f(w1));
                S1b = add2(S1b, k);
                S2b = fma2(k, yq23, S2b); }
        }
    }

    // Epilogue: acc = sum_lane [ yp*S1 + (1-2*yp)*S2 ],  then *2 (directed)
    float acc;
    {
        float s1_0, s1_1, s1_2, s1_3, s2_0, s2_1, s2_2, s2_3;
        upk(s1_0, s1_1, S1a); upk(s1_2, s1_3, S1b);
        upk(s2_0, s2_1, S2a); upk(s2_2, s2_3, S2b);
        float a = yc.x * s1_0 + fmaf(-2.0f * yc.x, s2_0, s2_0);
        a += yc.y * s1_1 + fmaf(-2.0f * yc.y, s2_1, s2_1);
        a += yc.z * s1_2 + fmaf(-2.0f * yc.z, s2_2, s2_2);
        a += yc.w * s1_3 + fmaf(-2.0f * yc.w, s2_3, s2_3);
        acc = a * 2.0f;
    }

    // Out-of-bounds slots: zero-padded features ->
    // k_oob = exp(-0.5*(fr^2+fc^2+fs^2)) per pixel, times OOB slot count.
    {
        const int ir = min(i + 3, H - 1) - max(i - 3, 0) + 1;
        const int ic = min(j + 3, W - 1) - max(j - 3, 0) + 1;
        const float cnt = (float)(49 - ir * ic);
        if (cnt > 0.0f) {
            const float cij = -(float)(i * i + j * j) * HALFL2E;
            float a0, a1, a2, a3;
            upk(a0, a1, na01); upk(a2, a3, na23);
            float e = ex2f(fmaf(a0, -a0, cij))
                    + ex2f(fmaf(a1, -a1, cij))
                    + ex2f(fmaf(a2, -a2, cij))
                    + ex2f(fmaf(a3, -a3, cij));
            acc = fmaf(cnt, e, acc);
        }
    }

    // ---- Warp shuffle reduction (5 SHFL), one barrier, one atomic ----
    #pragma unroll
    for (int o = 16; o > 0; o >>= 1)
        acc += __shfl_down_sync(0xffffffffu, acc, o);

    __shared__ float wsum[4];
    const int wid = tid >> 5, lane = tid & 31;
    if (lane == 0) wsum[wid] = acc;
    __syncthreads();

    if (tid == 0) {
        const float s = (wsum[0] + wsum[1]) + (wsum[2] + wsum[3]);
        atomicAdd(&g_sum, s);
        __threadfence();   // release: my g_sum add before my count increment
        const unsigned v = atomicAdd(&g_count, 1u);
        if (v == (unsigned)(NBLK - 1)) {
            __threadfence();   // acquire: all g_sum adds visible
            const float tot = *((volatile float*)&g_sum);
            out[0] = tot / (float)(NN * D * H * W);
            g_sum = 0.0f;      // reset for next graph replay
            g_count = 0u;
        }
    }
}

extern "C" void kernel_launch(void* const* d_in, const int* in_sizes, int n_in,
                              void* d_out, int out_size)
{
    const float* y = (const float*)d_in[0];   // (2,2,64,64,64) softmax
    const float* s = (const float*)d_in[1];   // (2,1,64,64,64) sample
    if (n_in >= 2 && in_sizes[0] == 2 * 1 * H * W * D) {
        const float* tmp = y; y = s; s = tmp;
    }

    dim3 blk(16, 8);
    crf_main<<<NBLK, blk>>>(y, s, (float*)d_out);
}

// round 10
// speedup vs baseline: 1.6441x; 1.2607x over previous
#include <cuda_runtime.h>

typedef unsigned long long u64;

// Problem constants: N=2, C=2, H=W=D=64, R=3, WEIGHT=1, SIGMA_XY=6, SIGMA_IMG=0.1
static constexpr int H = 64, W = 64, D = 64, NN = 2;
static constexpr int NBLK = 2 * 64 * 8;   // n(2) * i(64) * jc(8) = 1024 blocks

__device__ float g_sum = 0.0f;
__device__ unsigned int g_count = 0;

__device__ __forceinline__ float ex2f(float x) {
    float y;
    asm("ex2.approx.ftz.f32 %0, %1;" : "=f"(y) : "f"(x));
    return y;
}
__device__ __forceinline__ u64 pk(float a, float b) {
    u64 r; asm("mov.b64 %0, {%1, %2};" : "=l"(r) : "f"(a), "f"(b)); return r;
}
__device__ __forceinline__ void upk(float& a, float& b, u64 v) {
    asm("mov.b64 {%0, %1}, %2;" : "=f"(a), "=f"(b) : "l"(v));
}
__device__ __forceinline__ u64 fma2(u64 a, u64 b, u64 c) {
    u64 r; asm("fma.rn.f32x2 %0, %1, %2, %3;" : "=l"(r) : "l"(a), "l"(b), "l"(c)); return r;
}
__device__ __forceinline__ u64 add2(u64 a, u64 b) {
    u64 r; asm("add.rn.f32x2 %0, %1, %2;" : "=l"(r) : "l"(a), "l"(b)); return r;
}
__device__ __forceinline__ u64 mul2(u64 a, u64 b) {
    u64 r; asm("mul.rn.f32x2 %0, %1, %2;" : "=l"(r) : "l"(a), "l"(b)); return r;
}

// KS = sqrt(50 * log2(e))
#define KS 8.4932180864f
#define HALFL2E 0.0200373478f  /* 0.5/36 * log2(e) */
#define NEGBIG -1.0e30f

__global__ __launch_bounds__(128) void crf_main(
    const float* __restrict__ yg, const float* __restrict__ sg,
    float* __restrict__ out)
{
    const int d4 = threadIdx.x;          // 0..15  (4 d-values)
    const int ty = threadIdx.y;          // 0..7   (j within 8-col chunk)
    const int b  = blockIdx.x;
    const int jc = b & 7;
    const int i  = (b >> 3) & 63;
    const int n  = b >> 9;
    const int j  = jc * 8 + ty;
    const int tid = ty * 16 + d4;        // 0..127

    const float4* __restrict__ s4 = (const float4*)sg;
    const float4* __restrict__ y4 = (const float4*)yg;

    // sample layout: ((n*H + i)*W + j)*D + d   -> float4 index
    const int bs = (n * H + i) * (W * 16) + j * 16 + d4;
    // y channel 0: (((n*2)*H + i)*W + j)*D + d
    const int by = (n * 2 * H + i) * (W * 16) + j * 16 + d4;

    const float4 sc = s4[bs];
    const float4 yc = y4[by];

    const u64 KS2  = pk(KS, KS);
    const u64 NKS2 = pk(-KS, -KS);

    const u64 s01 = pk(sc.x, sc.y), s23 = pk(sc.z, sc.w);
    const u64 na01 = mul2(NKS2, s01), na23 = mul2(NKS2, s23);  // -KS*sc
    const u64 pa01 = mul2(KS2,  s01), pa23 = mul2(KS2,  s23);  // +KS*sc

    u64 S1a = 0ull, S1b = 0ull;   // sum of k
    u64 S2a = 0ull, S2b = 0ull;   // sum of k*yq

    // One unordered-pair offset (positive half-window), branchless OOB:
    // offset clamped to center, lw -> -1e30 => ex2 == 0.
    auto body = [&](int di, int dj) {
        const float lw = -(float)(di * di + dj * dj) * HALFL2E;
        const bool v = ((i + di) < H) & ((unsigned)(j + dj) < (unsigned)W);
        const int off = v ? (di * W + dj) * 16 : 0;
        const float lwv = v ? lw : NEGBIG;
        const u64 lw2 = pk(lwv, lwv);

        const float4 sq = s4[bs + off];
        const float4 yq = y4[by + off];
        const u64 sq01 = pk(sq.x, sq.y), sq23 = pk(sq.z, sq.w);
        const u64 yq01 = pk(yq.x, yq.y), yq23 = pk(yq.z, yq.w);

        {   const u64 t  = fma2(KS2,  sq01, na01);
            const u64 nt = fma2(NKS2, sq01, pa01);
            const u64 w  = fma2(t, nt, lw2);
            float w0, w1; upk(w0, w1, w);
            const u64 k = pk(ex2f(w0), ex2f(w1));
            S1a = add2(S1a, k);
            S2a = fma2(k, yq01, S2a); }
        {   const u64 t  = fma2(KS2,  sq23, na23);
            const u64 nt = fma2(NKS2, sq23, pa23);
            const u64 w  = fma2(t, nt, lw2);
            float w0, w1; upk(w0, w1, w);
            const u64 k = pk(ex2f(w0), ex2f(w1));
            S1b = add2(S1b, k);
            S2b = fma2(k, yq23, S2b); }
    };

    body(0, 1); body(0, 2); body(0, 3);
    body(1, -3); body(1, -2); body(1, -1); body(1, 0);
    body(1, 1); body(1, 2); body(1, 3);
    body(2, -3); body(2, -2); body(2, -1); body(2, 0);
    body(2, 1); body(2, 2); body(2, 3);
    body(3, -3); body(3, -2); body(3, -1); body(3, 0);
    body(3, 1); body(3, 2); body(3, 3);

    // Epilogue: acc = sum_lane [ yp*S1 + (1-2*yp)*S2 ],  then *2 (directed)
    float acc;
    {
        float s1_0, s1_1, s1_2, s1_3, s2_0, s2_1, s2_2, s2_3;
        upk(s1_0, s1_1, S1a); upk(s1_2, s1_3, S1b);
        upk(s2_0, s2_1, S2a); upk(s2_2, s2_3, S2b);
        float a = yc.x * s1_0 + fmaf(-2.0f * yc.x, s2_0, s2_0);
        a += yc.y * s1_1 + fmaf(-2.0f * yc.y, s2_1, s2_1);
        a += yc.z * s1_2 + fmaf(-2.0f * yc.z, s2_2, s2_2);
        a += yc.w * s1_3 + fmaf(-2.0f * yc.w, s2_3, s2_3);
        acc = a * 2.0f;
    }

    // Out-of-bounds slots: zero-padded features ->
    // k_oob = exp(-0.5*(fr^2+fc^2+fs^2)) per pixel, times OOB slot count.
    {
        const int ir = min(i + 3, H - 1) - max(i - 3, 0) + 1;
        const int ic = min(j + 3, W - 1) - max(j - 3, 0) + 1;
        const float cnt = (float)(49 - ir * ic);
        if (cnt > 0.0f) {
            const float cij = -(float)(i * i + j * j) * HALFL2E;
            float a0, a1, a2, a3;
            upk(a0, a1, na01); upk(a2, a3, na23);
            float e = ex2f(fmaf(a0, -a0, cij))
                    + ex2f(fmaf(a1, -a1, cij))
                    + ex2f(fmaf(a2, -a2, cij))
                    + ex2f(fmaf(a3, -a3, cij));
            acc = fmaf(cnt, e, acc);
        }
    }

    // ---- Warp shuffle reduction (5 SHFL), one barrier, one atomic ----
    #pragma unroll
    for (int o = 16; o > 0; o >>= 1)
        acc += __shfl_down_sync(0xffffffffu, acc, o);

    __shared__ float wsum[4];
    const int wid = tid >> 5, lane = tid & 31;
    if (lane == 0) wsum[wid] = acc;
    __syncthreads();

    if (tid == 0) {
        const float s = (wsum[0] + wsum[1]) + (wsum[2] + wsum[3]);
        atomicAdd(&g_sum, s);
        __threadfence();   // release: my g_sum add before my count increment
        const unsigned v = atomicAdd(&g_count, 1u);
        if (v == (unsigned)(NBLK - 1)) {
            __threadfence();   // acquire: all g_sum adds visible
            const float tot = *((volatile float*)&g_sum);
            out[0] = tot / (float)(NN * D * H * W);
            g_sum = 0.0f;      // reset for next graph replay
            g_count = 0u;
        }
    }
}

extern "C" void kernel_launch(void* const* d_in, const int* in_sizes, int n_in,
                              void* d_out, int out_size)
{
    const float* y = (const float*)d_in[0];   // (2,2,64,64,64) softmax
    const float* s = (const float*)d_in[1];   // (2,1,64,64,64) sample
    if (n_in >= 2 && in_sizes[0] == 2 * 1 * H * W * D) {
        const float* tmp = y; y = s; s = tmp;
    }

    dim3 blk(16, 8);
    crf_main<<<NBLK, blk>>>(y, s, (float*)d_out);
}